// round 1
// baseline (speedup 1.0000x reference)
#include <cuda_runtime.h>
#include <math.h>

#define BATCH   2048
#define DIM     200
#define OCH     64
#define NPIX    400          // 20x20
#define FLATK   25600        // 64*400
#define NENT    50000
#define EPSF    1e-5f

// ---------------- scratch (static device globals; no allocs) ----------------
__device__ float g_X[BATCH * NPIX];                    // permuted inputs (B,400)
__device__ float g_Y[(size_t)BATCH * OCH * NPIX];      // raw conv output (B,25600) ~210MB
__device__ float g_H[BATCH * DIM];                     // fc output pre-bn
__device__ float g_H2[BATCH * DIM];                    // post bn1d + relu
__device__ float g_sums[2];                            // bn0 sum, sumsq
__device__ float g_csum[OCH];                          // per-channel conv sums
__device__ float g_csumsq[OCH];
__device__ float g_scale[OCH];                         // composed BN scale/shift
__device__ float g_shift[OCH];

// ---------------- init: zero atomic accumulators ----------------
__global__ void k_init() {
    int t = threadIdx.x;
    if (t < 2) g_sums[t] = 0.f;
    if (t < OCH) { g_csum[t] = 0.f; g_csumsq[t] = 0.f; }
}

// ---------------- gather + chequer permutation + bn0 stats ----------------
// PERM[q]: r=q/20, c=q%20 -> useB=(r+c)&1, idx = r*10 + c/2
__global__ void k_gather(const float* __restrict__ nf, const float* __restrict__ rf,
                         const int* __restrict__ sub, const int* __restrict__ rel) {
    int b = blockIdx.x;
    int t = threadIdx.x;   // 512
    float v = 0.f;
    if (t < NPIX) {
        int r = t / 20, c = t % 20;
        int idx = r * 10 + (c >> 1);
        int useB = (r + c) & 1;
        v = useB ? rf[rel[b] * DIM + idx]
                 : nf[(size_t)sub[b] * DIM + idx];
        g_X[b * NPIX + t] = v;
    }
    __shared__ float ss[512], sq[512];
    ss[t] = v; sq[t] = v * v;
    __syncthreads();
    for (int s = 256; s > 0; s >>= 1) {
        if (t < s) { ss[t] += ss[t + s]; sq[t] += sq[t + s]; }
        __syncthreads();
    }
    if (t == 0) { atomicAdd(&g_sums[0], ss[0]); atomicAdd(&g_sums[1], sq[0]); }
}

// ---------------- per-sample dynamic conv + per-channel stats ----------------
__global__ void k_conv(const float* __restrict__ fw, const int* __restrict__ rel,
                       const float* __restrict__ bn0g, const float* __restrict__ bn0b) {
    int b = blockIdx.x;
    int t = threadIdx.x;   // 256
    __shared__ float xs[22 * 22];   // zero-padded normalized image
    __shared__ float fs[OCH * 9];

    float invN = 1.0f / (float)(BATCH * NPIX);
    float m0 = g_sums[0] * invN;
    float v0 = g_sums[1] * invN - m0 * m0;
    float sc0 = bn0g[0] * rsqrtf(v0 + EPSF);
    float sh0 = bn0b[0] - sc0 * m0;

    for (int i = t; i < 484; i += 256) {
        int ph = i / 22, pw = i % 22;
        float val = 0.f;
        if (ph >= 1 && ph <= 20 && pw >= 1 && pw <= 20)
            val = sc0 * g_X[b * NPIX + (ph - 1) * 20 + (pw - 1)] + sh0;
        xs[i] = val;
    }
    int rb = rel[b];
    for (int i = t; i < OCH * 9; i += 256) fs[i] = fw[rb * (OCH * 9) + i];
    __syncthreads();

    int oc = t >> 2, l4 = t & 3;
    float f[9];
#pragma unroll
    for (int j = 0; j < 9; j++) f[j] = fs[oc * 9 + j];

    float s1 = 0.f, s2 = 0.f;
    float* ybase = &g_Y[((size_t)b * OCH + oc) * NPIX];
#pragma unroll 4
    for (int s = 0; s < 100; s++) {
        int pix = l4 + 4 * s;
        int h = pix / 20, w = pix % 20;
        const float* xp = &xs[h * 22 + w];
        float acc = xp[0]  * f[0] + xp[1]  * f[1] + xp[2]  * f[2]
                  + xp[22] * f[3] + xp[23] * f[4] + xp[24] * f[5]
                  + xp[44] * f[6] + xp[45] * f[7] + xp[46] * f[8];
        ybase[pix] = acc;
        s1 += acc; s2 += acc * acc;
    }
    // reduce within 4-lane group (same oc)
    s1 += __shfl_down_sync(0xffffffffu, s1, 2, 4);
    s1 += __shfl_down_sync(0xffffffffu, s1, 1, 4);
    s2 += __shfl_down_sync(0xffffffffu, s2, 2, 4);
    s2 += __shfl_down_sync(0xffffffffu, s2, 1, 4);
    if (l4 == 0) { atomicAdd(&g_csum[oc], s1); atomicAdd(&g_csumsq[oc], s2); }
}

// ---------------- compose the two BN2d into scale/shift per channel ----------------
__global__ void k_chan(const float* __restrict__ cg, const float* __restrict__ cb,
                       const float* __restrict__ b1g, const float* __restrict__ b1b) {
    int t = threadIdx.x;   // 64
    if (t >= OCH) return;
    float invN = 1.0f / (float)(BATCH * NPIX);
    float m = g_csum[t] * invN;
    float v = g_csumsq[t] * invN - m * m;
    float t1 = rsqrtf(v + EPSF);
    float var1 = cg[t] * cg[t] * v * t1 * t1;   // gamma^2 * v/(v+eps)
    float t2 = rsqrtf(var1 + EPSF);
    float sc = b1g[t] * cg[t] * t1 * t2;
    g_scale[t] = sc;
    g_shift[t] = b1b[t] - sc * m;
}

// ---------------- FC GEMM: H = relu(bn(Y)) @ fc_w^T + fc_b ----------------
// M=2048 (64-tiles), N=200 (40-tiles), K=25600 (32-chunks)
__global__ __launch_bounds__(256) void k_fc(const float* __restrict__ fw,
                                            const float* __restrict__ fb) {
    __shared__ float As[32][64];
    __shared__ float Bs[32][40];
    __shared__ float sSc[OCH], sSh[OCH];
    int n0 = blockIdx.x * 40;
    int m0 = blockIdx.y * 64;
    int t = threadIdx.x;
    int tm = t >> 3, tn = t & 7;   // 32 x 8
    if (t < OCH) { sSc[t] = g_scale[t]; sSh[t] = g_shift[t]; }
    __syncthreads();

    float acc[2][5] = {};
    for (int k0 = 0; k0 < FLATK; k0 += 32) {
#pragma unroll
        for (int r = 0; r < 8; r++) {
            int li = t + 256 * r;
            int row = li >> 5, col = li & 31;
            int kg = k0 + col;
            int oc = kg / NPIX;
            float y = g_Y[(size_t)(m0 + row) * FLATK + kg];
            float z = sSc[oc] * y + sSh[oc];
            As[col][row] = z > 0.f ? z : 0.f;
        }
#pragma unroll
        for (int r = 0; r < 5; r++) {
            int li = t + 256 * r;
            int row = li >> 5, col = li & 31;
            Bs[col][row] = fw[(size_t)(n0 + row) * FLATK + k0 + col];
        }
        __syncthreads();
#pragma unroll
        for (int kk = 0; kk < 32; kk++) {
            float a0 = As[kk][tm * 2];
            float a1 = As[kk][tm * 2 + 1];
#pragma unroll
            for (int j = 0; j < 5; j++) {
                float bb = Bs[kk][tn * 5 + j];
                acc[0][j] += a0 * bb;
                acc[1][j] += a1 * bb;
            }
        }
        __syncthreads();
    }
#pragma unroll
    for (int i = 0; i < 2; i++)
#pragma unroll
        for (int j = 0; j < 5; j++) {
            int m = m0 + tm * 2 + i, n = n0 + tn * 5 + j;
            g_H[m * DIM + n] = acc[i][j] + fb[n];
        }
}

// ---------------- bn1d over batch per feature + relu ----------------
__global__ void k_bn1d(const float* __restrict__ b2g, const float* __restrict__ b2b) {
    int d = blockIdx.x;     // 200 blocks
    int t = threadIdx.x;    // 256
    float vals[8];
    float s1 = 0.f, s2 = 0.f;
#pragma unroll
    for (int i = 0; i < 8; i++) {
        float h = g_H[(t + 256 * i) * DIM + d];
        vals[i] = h; s1 += h; s2 += h * h;
    }
    __shared__ float ss[256], sq[256];
    ss[t] = s1; sq[t] = s2;
    __syncthreads();
    for (int s = 128; s > 0; s >>= 1) {
        if (t < s) { ss[t] += ss[t + s]; sq[t] += sq[t + s]; }
        __syncthreads();
    }
    __shared__ float ssc, ssh;
    if (t == 0) {
        float m = ss[0] / (float)BATCH;
        float v = sq[0] / (float)BATCH - m * m;
        float sc = b2g[d] * rsqrtf(v + EPSF);
        ssc = sc; ssh = b2b[d] - sc * m;
    }
    __syncthreads();
    float sc = ssc, sh = ssh;
#pragma unroll
    for (int i = 0; i < 8; i++) {
        float z = sc * vals[i] + sh;
        g_H2[(t + 256 * i) * DIM + d] = z > 0.f ? z : 0.f;
    }
}

// ---------------- scoring GEMM: out = H2 @ n_feats^T + ent_bias ----------------
// M=2048 (128-tiles), N=50000 (128-tiles, 391), K=200 (40-chunks)
__global__ __launch_bounds__(256, 2) void k_out(const float* __restrict__ nf,
                                                const float* __restrict__ eb,
                                                float* __restrict__ out) {
    __shared__ float As[40 * 128];
    __shared__ float Bs[40 * 128];
    int n0 = blockIdx.x * 128;
    int m0 = blockIdx.y * 128;
    int t = threadIdx.x;
    int tx = t & 15, ty = t >> 4;   // 16 x 16
    float acc[8][8] = {};

    for (int k0 = 0; k0 < DIM; k0 += 40) {
#pragma unroll
        for (int r = 0; r < 20; r++) {
            int li = t + 256 * r;
            int col = li % 40, row = li / 40;
            As[col * 128 + row] = g_H2[(m0 + row) * DIM + k0 + col];
            int n = n0 + row;
            Bs[col * 128 + row] = (n < NENT) ? nf[(size_t)n * DIM + k0 + col] : 0.f;
        }
        __syncthreads();
#pragma unroll 4
        for (int kk = 0; kk < 40; kk++) {
            float4 aLo = *(const float4*)&As[kk * 128 + ty * 4];
            float4 aHi = *(const float4*)&As[kk * 128 + 64 + ty * 4];
            float4 bLo = *(const float4*)&Bs[kk * 128 + tx * 4];
            float4 bHi = *(const float4*)&Bs[kk * 128 + 64 + tx * 4];
            float a[8] = {aLo.x, aLo.y, aLo.z, aLo.w, aHi.x, aHi.y, aHi.z, aHi.w};
            float bv[8] = {bLo.x, bLo.y, bLo.z, bLo.w, bHi.x, bHi.y, bHi.z, bHi.w};
#pragma unroll
            for (int i = 0; i < 8; i++)
#pragma unroll
                for (int j = 0; j < 8; j++)
                    acc[i][j] += a[i] * bv[j];
        }
        __syncthreads();
    }

    int c0 = n0 + tx * 4;
    int c1 = n0 + 64 + tx * 4;
#pragma unroll
    for (int i = 0; i < 8; i++) {
        int m = m0 + ((i < 4) ? (ty * 4 + i) : (64 + ty * 4 + i - 4));
        if (c0 < NENT) {
            float4 v = {acc[i][0] + eb[c0], acc[i][1] + eb[c0 + 1],
                        acc[i][2] + eb[c0 + 2], acc[i][3] + eb[c0 + 3]};
            *(float4*)&out[(size_t)m * NENT + c0] = v;
        }
        if (c1 < NENT) {
            float4 v = {acc[i][4] + eb[c1], acc[i][5] + eb[c1 + 1],
                        acc[i][6] + eb[c1 + 2], acc[i][7] + eb[c1 + 3]};
            *(float4*)&out[(size_t)m * NENT + c1] = v;
        }
    }
}

// ---------------- launch ----------------
extern "C" void kernel_launch(void* const* d_in, const int* in_sizes, int n_in,
                              void* d_out, int out_size) {
    const float* nf   = (const float*)d_in[0];
    const float* rf   = (const float*)d_in[1];
    const float* fw   = (const float*)d_in[2];
    const float* bn0g = (const float*)d_in[3];
    const float* bn0b = (const float*)d_in[4];
    const float* cbng = (const float*)d_in[5];
    const float* cbnb = (const float*)d_in[6];
    const float* bn1g = (const float*)d_in[7];
    const float* bn1b = (const float*)d_in[8];
    const float* fcw  = (const float*)d_in[9];
    const float* fcb  = (const float*)d_in[10];
    const float* bn2g = (const float*)d_in[11];
    const float* bn2b = (const float*)d_in[12];
    const float* eb   = (const float*)d_in[13];
    const int*   sub  = (const int*)d_in[14];
    const int*   rel  = (const int*)d_in[15];
    float* out = (float*)d_out;

    k_init<<<1, 256>>>();
    k_gather<<<BATCH, 512>>>(nf, rf, sub, rel);
    k_conv<<<BATCH, 256>>>(fw, rel, bn0g, bn0b);
    k_chan<<<1, 64>>>(cbng, cbnb, bn1g, bn1b);
    k_fc<<<dim3(5, 32), 256>>>(fcw, fcb);
    k_bn1d<<<DIM, 256>>>(bn2g, bn2b);
    k_out<<<dim3((NENT + 127) / 128, BATCH / 128), 256>>>(nf, eb, out);
}

// round 4
// speedup vs baseline: 1.2508x; 1.2508x over previous
#include <cuda_runtime.h>
#include <cuda_bf16.h>
#include <math.h>
#include <stdint.h>

#define BATCH   2048
#define DIM     200
#define OCH     64
#define NPIX    400          // 20x20
#define FLATK   25600        // 64*400
#define NENT    50000
#define EPSF    1e-5f

#define KPASS   256          // per-pass padded K (200 -> 256)
#define KTOT    768          // 3 passes concatenated
#define NTILE   128
#define NTILES  391          // ceil(50000/128)
#define NENTP   (NTILES*NTILE)   // 50048

// ---------------- scratch (static device globals; no allocs) ----------------
__device__ float g_X[BATCH * NPIX];
__device__ float g_Y[(size_t)BATCH * OCH * NPIX];      // raw conv output ~210MB
__device__ float g_H[BATCH * DIM];                     // fc output pre-bn
__device__ float g_sums[2];
__device__ float g_csum[OCH];
__device__ float g_csumsq[OCH];
__device__ float g_scale[OCH];
__device__ float g_shift[OCH];
// concatenated hi/lo bf16 operands: A' = [Ah|Ah|Al], B' = [Bh|Bl|Bh]
__device__ __nv_bfloat16 g_ap[(size_t)BATCH * KTOT];   // 3MB
__device__ __nv_bfloat16 g_bp[(size_t)NENTP * KTOT];   // 77MB

// ---------------- init ----------------
__global__ void k_init() {
    int t = threadIdx.x;
    if (t < 2) g_sums[t] = 0.f;
    if (t < OCH) { g_csum[t] = 0.f; g_csumsq[t] = 0.f; }
}

// ---------------- gather + chequer perm + bn0 stats ----------------
__global__ void k_gather(const float* __restrict__ nf, const float* __restrict__ rf,
                         const int* __restrict__ sub, const int* __restrict__ rel) {
    int b = blockIdx.x;
    int t = threadIdx.x;   // 512
    float v = 0.f;
    if (t < NPIX) {
        int r = t / 20, c = t % 20;
        int idx = r * 10 + (c >> 1);
        int useB = (r + c) & 1;
        v = useB ? rf[rel[b] * DIM + idx]
                 : nf[(size_t)sub[b] * DIM + idx];
        g_X[b * NPIX + t] = v;
    }
    __shared__ float ss[512], sq[512];
    ss[t] = v; sq[t] = v * v;
    __syncthreads();
    for (int s = 256; s > 0; s >>= 1) {
        if (t < s) { ss[t] += ss[t + s]; sq[t] += sq[t + s]; }
        __syncthreads();
    }
    if (t == 0) { atomicAdd(&g_sums[0], ss[0]); atomicAdd(&g_sums[1], sq[0]); }
}

// ---------------- per-sample dynamic conv + per-channel stats ----------------
__global__ void k_conv(const float* __restrict__ fw, const int* __restrict__ rel,
                       const float* __restrict__ bn0g, const float* __restrict__ bn0b) {
    int b = blockIdx.x;
    int t = threadIdx.x;   // 256
    __shared__ float xs[22 * 22];
    __shared__ float fs[OCH * 9];

    float invN = 1.0f / (float)(BATCH * NPIX);
    float m0 = g_sums[0] * invN;
    float v0 = g_sums[1] * invN - m0 * m0;
    float sc0 = bn0g[0] * rsqrtf(v0 + EPSF);
    float sh0 = bn0b[0] - sc0 * m0;

    for (int i = t; i < 484; i += 256) {
        int ph = i / 22, pw = i % 22;
        float val = 0.f;
        if (ph >= 1 && ph <= 20 && pw >= 1 && pw <= 20)
            val = sc0 * g_X[b * NPIX + (ph - 1) * 20 + (pw - 1)] + sh0;
        xs[i] = val;
    }
    int rb = rel[b];
    for (int i = t; i < OCH * 9; i += 256) fs[i] = fw[rb * (OCH * 9) + i];
    __syncthreads();

    int oc = t >> 2, l4 = t & 3;
    float f[9];
#pragma unroll
    for (int j = 0; j < 9; j++) f[j] = fs[oc * 9 + j];

    float s1 = 0.f, s2 = 0.f;
    float* ybase = &g_Y[((size_t)b * OCH + oc) * NPIX];
#pragma unroll 4
    for (int s = 0; s < 100; s++) {
        int pix = l4 + 4 * s;
        int h = pix / 20, w = pix % 20;
        const float* xp = &xs[h * 22 + w];
        float acc = xp[0]  * f[0] + xp[1]  * f[1] + xp[2]  * f[2]
                  + xp[22] * f[3] + xp[23] * f[4] + xp[24] * f[5]
                  + xp[44] * f[6] + xp[45] * f[7] + xp[46] * f[8];
        ybase[pix] = acc;
        s1 += acc; s2 += acc * acc;
    }
    s1 += __shfl_down_sync(0xffffffffu, s1, 2, 4);
    s1 += __shfl_down_sync(0xffffffffu, s1, 1, 4);
    s2 += __shfl_down_sync(0xffffffffu, s2, 2, 4);
    s2 += __shfl_down_sync(0xffffffffu, s2, 1, 4);
    if (l4 == 0) { atomicAdd(&g_csum[oc], s1); atomicAdd(&g_csumsq[oc], s2); }
}

// ---------------- compose the two BN2d ----------------
__global__ void k_chan(const float* __restrict__ cg, const float* __restrict__ cb,
                       const float* __restrict__ b1g, const float* __restrict__ b1b) {
    int t = threadIdx.x;
    if (t >= OCH) return;
    float invN = 1.0f / (float)(BATCH * NPIX);
    float m = g_csum[t] * invN;
    float v = g_csumsq[t] * invN - m * m;
    float t1 = rsqrtf(v + EPSF);
    float var1 = cg[t] * cg[t] * v * t1 * t1;
    float t2 = rsqrtf(var1 + EPSF);
    float sc = b1g[t] * cg[t] * t1 * t2;
    g_scale[t] = sc;
    g_shift[t] = b1b[t] - sc * m;
}

// ---------------- build B' = [Bh | Bl | Bh] from n_feats ----------------
__global__ void k_cvt_nf(const float* __restrict__ nf) {
    int n = blockIdx.x;      // 0..NENTP-1
    int k = threadIdx.x;     // 0..255
    float x = 0.f;
    if (n < NENT && k < DIM) x = nf[(size_t)n * DIM + k];
    __nv_bfloat16 hi = __float2bfloat16(x);
    float lo = x - __bfloat162float(hi);
    __nv_bfloat16 lo16 = __float2bfloat16(lo);
    size_t base = (size_t)n * KTOT + k;
    g_bp[base] = hi;
    g_bp[base + KPASS] = lo16;
    g_bp[base + 2 * KPASS] = hi;
}

// ---------------- FC GEMM (SIMT) ----------------
__global__ __launch_bounds__(256) void k_fc(const float* __restrict__ fw,
                                            const float* __restrict__ fb) {
    __shared__ float As[32][64];
    __shared__ float Bs[32][40];
    __shared__ float sSc[OCH], sSh[OCH];
    int n0 = blockIdx.x * 40;
    int m0 = blockIdx.y * 64;
    int t = threadIdx.x;
    int tm = t >> 3, tn = t & 7;
    if (t < OCH) { sSc[t] = g_scale[t]; sSh[t] = g_shift[t]; }
    __syncthreads();

    float acc[2][5] = {};
    for (int k0 = 0; k0 < FLATK; k0 += 32) {
#pragma unroll
        for (int r = 0; r < 8; r++) {
            int li = t + 256 * r;
            int row = li >> 5, col = li & 31;
            int kg = k0 + col;
            int oc = kg / NPIX;
            float y = g_Y[(size_t)(m0 + row) * FLATK + kg];
            float z = sSc[oc] * y + sSh[oc];
            As[col][row] = z > 0.f ? z : 0.f;
        }
#pragma unroll
        for (int r = 0; r < 5; r++) {
            int li = t + 256 * r;
            int row = li >> 5, col = li & 31;
            Bs[col][row] = fw[(size_t)(n0 + row) * FLATK + k0 + col];
        }
        __syncthreads();
#pragma unroll
        for (int kk = 0; kk < 32; kk++) {
            float a0 = As[kk][tm * 2];
            float a1 = As[kk][tm * 2 + 1];
#pragma unroll
            for (int j = 0; j < 5; j++) {
                float bb = Bs[kk][tn * 5 + j];
                acc[0][j] += a0 * bb;
                acc[1][j] += a1 * bb;
            }
        }
        __syncthreads();
    }
#pragma unroll
    for (int i = 0; i < 2; i++)
#pragma unroll
        for (int j = 0; j < 5; j++) {
            int m = m0 + tm * 2 + i, n = n0 + tn * 5 + j;
            g_H[m * DIM + n] = acc[i][j] + fb[n];
        }
}

// ---------------- bn1d + relu -> A' = [Ah | Ah | Al] ----------------
__global__ void k_bn1d(const float* __restrict__ b2g, const float* __restrict__ b2b) {
    int d = blockIdx.x;     // 0..255
    int t = threadIdx.x;    // 256
    __nv_bfloat16 z16 = __float2bfloat16(0.f);
    if (d >= DIM) {
        for (int i = t; i < BATCH; i += 256) {
            size_t base = (size_t)i * KTOT + d;
            g_ap[base] = z16; g_ap[base + KPASS] = z16; g_ap[base + 2 * KPASS] = z16;
        }
        return;
    }
    float vals[8];
    float s1 = 0.f, s2 = 0.f;
#pragma unroll
    for (int i = 0; i < 8; i++) {
        float h = g_H[(t + 256 * i) * DIM + d];
        vals[i] = h; s1 += h; s2 += h * h;
    }
    __shared__ float ss[256], sq[256];
    ss[t] = s1; sq[t] = s2;
    __syncthreads();
    for (int s = 128; s > 0; s >>= 1) {
        if (t < s) { ss[t] += ss[t + s]; sq[t] += sq[t + s]; }
        __syncthreads();
    }
    __shared__ float ssc, ssh;
    if (t == 0) {
        float m = ss[0] / (float)BATCH;
        float v = sq[0] / (float)BATCH - m * m;
        float sc = b2g[d] * rsqrtf(v + EPSF);
        ssc = sc; ssh = b2b[d] - sc * m;
    }
    __syncthreads();
    float sc = ssc, sh = ssh;
#pragma unroll
    for (int i = 0; i < 8; i++) {
        float z = sc * vals[i] + sh;
        z = z > 0.f ? z : 0.f;
        __nv_bfloat16 hi = __float2bfloat16(z);
        float lo = z - __bfloat162float(hi);
        size_t base = (size_t)(t + 256 * i) * KTOT + d;
        g_ap[base] = hi;
        g_ap[base + KPASS] = hi;
        g_ap[base + 2 * KPASS] = __float2bfloat16(lo);
    }
}

// ---------------- mma.sync helpers ----------------
__device__ __forceinline__ uint32_t cvta_smem(const void* p) {
    uint32_t a;
    asm("{ .reg .u64 t; cvta.to.shared.u64 t, %1; cvt.u32.u64 %0, t; }" : "=r"(a) : "l"(p));
    return a;
}
__device__ __forceinline__ void ldsm_x4(uint32_t& r0, uint32_t& r1, uint32_t& r2, uint32_t& r3,
                                        uint32_t addr) {
    asm volatile("ldmatrix.sync.aligned.m8n8.x4.shared.b16 {%0,%1,%2,%3}, [%4];"
                 : "=r"(r0), "=r"(r1), "=r"(r2), "=r"(r3) : "r"(addr));
}
__device__ __forceinline__ void mma_bf16(float& d0, float& d1, float& d2, float& d3,
                                         uint32_t a0, uint32_t a1, uint32_t a2, uint32_t a3,
                                         uint32_t b0, uint32_t b1) {
    asm volatile("mma.sync.aligned.m16n8k16.row.col.f32.bf16.bf16.f32 "
                 "{%0,%1,%2,%3}, {%4,%5,%6,%7}, {%8,%9}, {%0,%1,%2,%3};"
                 : "+f"(d0), "+f"(d1), "+f"(d2), "+f"(d3)
                 : "r"(a0), "r"(a1), "r"(a2), "r"(a3), "r"(b0), "r"(b1));
}

// ---------------- scoring GEMM via mma.sync (bf16, K'=768) ----------------
// CTA 128x128, 8 warps (2 along M x 4 along N), warp tile 64x32, K chunk 64.
__global__ __launch_bounds__(256, 2) void k_out_mma(const float* __restrict__ eb,
                                                    float* __restrict__ out) {
    __shared__ __align__(1024) __nv_bfloat16 smA[128 * 64];   // 16KB, SW128-swizzled rows
    __shared__ __align__(1024) __nv_bfloat16 smB[128 * 64];   // 16KB

    int t = threadIdx.x;
    int lane = t & 31, wid = t >> 5;
    int wm = (wid >> 2) * 64;        // warp M offset (0,64)
    int wn = (wid & 3) * 32;         // warp N offset (0,32,64,96)
    int m0 = blockIdx.x * 128;
    int n0 = blockIdx.y * NTILE;

    uint32_t baseA = cvta_smem(smA);
    uint32_t baseB = cvta_smem(smB);

    // ldmatrix lane geometry
    int grp = lane >> 3, li = lane & 7;
    int roffA = ((grp & 1) << 3) + li;   // A row within 16
    int cgA = grp >> 1;                  // A k-half (0/1)
    int noffB = ((grp >> 1) << 3) + li;  // B row (n) within 16
    int cgB = grp & 1;                   // B k-half

    float acc[4][4][4];
#pragma unroll
    for (int a = 0; a < 4; a++)
#pragma unroll
        for (int b = 0; b < 4; b++)
#pragma unroll
            for (int c = 0; c < 4; c++) acc[a][b][c] = 0.f;

    const __nv_bfloat16* pA = g_ap + (size_t)m0 * KTOT;
    const __nv_bfloat16* pB = g_bp + (size_t)n0 * KTOT;

    for (int ch = 0; ch < 12; ch++) {
        // load 128x64 tiles (128B rows), SW128 swizzle
#pragma unroll
        for (int r = 0; r < 4; r++) {
            int e = t + 256 * r;
            int row = e >> 3, seg = e & 7;
            uint32_t so = (uint32_t)row * 128 + (uint32_t)((seg ^ (row & 7)) << 4);
            size_t go = (size_t)row * KTOT + ch * 64 + seg * 8;
            *(uint4*)((char*)smA + so) = *(const uint4*)(pA + go);
            *(uint4*)((char*)smB + so) = *(const uint4*)(pB + go);
        }
        __syncthreads();

#pragma unroll
        for (int kf = 0; kf < 4; kf++) {
            uint32_t a[4][4];
#pragma unroll
            for (int mf = 0; mf < 4; mf++) {
                int row = wm + mf * 16 + roffA;
                uint32_t addr = baseA + (uint32_t)row * 128
                              + (uint32_t)(((kf * 2 + cgA) ^ li) << 4);
                ldsm_x4(a[mf][0], a[mf][1], a[mf][2], a[mf][3], addr);
            }
            uint32_t b[4][2];
#pragma unroll
            for (int nf2 = 0; nf2 < 2; nf2++) {
                int row = wn + nf2 * 16 + noffB;
                uint32_t addr = baseB + (uint32_t)row * 128
                              + (uint32_t)(((kf * 2 + cgB) ^ li) << 4);
                ldsm_x4(b[nf2 * 2][0], b[nf2 * 2][1], b[nf2 * 2 + 1][0], b[nf2 * 2 + 1][1], addr);
            }
#pragma unroll
            for (int mf = 0; mf < 4; mf++)
#pragma unroll
                for (int nf = 0; nf < 4; nf++)
                    mma_bf16(acc[mf][nf][0], acc[mf][nf][1], acc[mf][nf][2], acc[mf][nf][3],
                             a[mf][0], a[mf][1], a[mf][2], a[mf][3],
                             b[nf][0], b[nf][1]);
        }
        __syncthreads();
    }

    // epilogue: direct stores with bias
    int g = lane >> 2, c = lane & 3;
#pragma unroll
    for (int mf = 0; mf < 4; mf++) {
#pragma unroll
        for (int nf = 0; nf < 4; nf++) {
            int n = n0 + wn + nf * 8 + c * 2;
            if (n < NENT) {
                float2 bias = *(const float2*)(eb + n);
                int m = m0 + wm + mf * 16 + g;
                float2 v0 = {acc[mf][nf][0] + bias.x, acc[mf][nf][1] + bias.y};
                *(float2*)(out + (size_t)m * NENT + n) = v0;
                float2 v1 = {acc[mf][nf][2] + bias.x, acc[mf][nf][3] + bias.y};
                *(float2*)(out + (size_t)(m + 8) * NENT + n) = v1;
            }
        }
    }
}

// ---------------- launch ----------------
extern "C" void kernel_launch(void* const* d_in, const int* in_sizes, int n_in,
                              void* d_out, int out_size) {
    const float* nf   = (const float*)d_in[0];
    const float* rf   = (const float*)d_in[1];
    const float* fw   = (const float*)d_in[2];
    const float* bn0g = (const float*)d_in[3];
    const float* bn0b = (const float*)d_in[4];
    const float* cbng = (const float*)d_in[5];
    const float* cbnb = (const float*)d_in[6];
    const float* bn1g = (const float*)d_in[7];
    const float* bn1b = (const float*)d_in[8];
    const float* fcw  = (const float*)d_in[9];
    const float* fcb  = (const float*)d_in[10];
    const float* bn2g = (const float*)d_in[11];
    const float* bn2b = (const float*)d_in[12];
    const float* eb   = (const float*)d_in[13];
    const int*   sub  = (const int*)d_in[14];
    const int*   rel  = (const int*)d_in[15];
    float* out = (float*)d_out;

    k_init<<<1, 256>>>();
    k_gather<<<BATCH, 512>>>(nf, rf, sub, rel);
    k_conv<<<BATCH, 256>>>(fw, rel, bn0g, bn0b);
    k_chan<<<1, 64>>>(cbng, cbnb, bn1g, bn1b);
    k_cvt_nf<<<NENTP, 256>>>(nf);
    k_fc<<<dim3(5, 32), 256>>>(fcw, fcb);
    k_bn1d<<<KPASS, 256>>>(bn2g, bn2b);
    k_out_mma<<<dim3(16, NTILES), 256>>>(eb, out);
}

// round 5
// speedup vs baseline: 5.8549x; 4.6808x over previous
#include <cuda_runtime.h>
#include <cuda_bf16.h>
#include <math.h>
#include <stdint.h>

#define BATCH   2048
#define DIM     200
#define OCH     64
#define NPIX    400          // 20x20
#define FLATK   25600        // 64*400
#define NENT    50000
#define EPSF    1e-5f

#define KPASS   256          // per-pass padded K for scoring GEMM (200 -> 256)
#define KTOT    768          // 3 passes concatenated
#define NTILE   128
#define NTILES  391          // ceil(50000/128)
#define NENTP   (NTILES*NTILE)   // 50048
#define KSPLIT  8
#define KSEG    (FLATK/KSPLIT)   // 3200
#define NPADFC  256

// ---------------- scratch (static device globals; no allocs) ----------------
__device__ float g_X[BATCH * NPIX];
__device__ float g_Y[(size_t)BATCH * FLATK];           // raw conv output ~210MB
__device__ float g_H[BATCH * DIM];                     // fc output pre-bn
__device__ float g_sums[2];
__device__ float g_csum[OCH];
__device__ float g_csumsq[OCH];
__device__ float g_scale[OCH];
__device__ float g_shift[OCH];
// scoring GEMM operands: A' = [Ah|Ah|Al], B' = [Bh|Bl|Bh]
__device__ __nv_bfloat16 g_ap[(size_t)BATCH * KTOT];   // 3MB
__device__ __nv_bfloat16 g_bp[(size_t)NENTP * KTOT];   // 77MB
// fc GEMM operands (hi/lo separate, 3 logical passes)
__device__ __nv_bfloat16 g_yh[(size_t)BATCH * FLATK];  // 105MB
__device__ __nv_bfloat16 g_yl[(size_t)BATCH * FLATK];  // 105MB
__device__ __nv_bfloat16 g_wh[(size_t)DIM * FLATK];    // 10.3MB
__device__ __nv_bfloat16 g_wl[(size_t)DIM * FLATK];
__device__ float g_hp[(size_t)KSPLIT * BATCH * NPADFC]; // fc partials 16.8MB

// ---------------- init ----------------
__global__ void k_init() {
    int t = threadIdx.x;
    if (t < 2) g_sums[t] = 0.f;
    if (t < OCH) { g_csum[t] = 0.f; g_csumsq[t] = 0.f; }
}

// ---------------- gather + chequer perm + bn0 stats ----------------
__global__ void k_gather(const float* __restrict__ nf, const float* __restrict__ rf,
                         const int* __restrict__ sub, const int* __restrict__ rel) {
    int b = blockIdx.x;
    int t = threadIdx.x;   // 512
    float v = 0.f;
    if (t < NPIX) {
        int r = t / 20, c = t % 20;
        int idx = r * 10 + (c >> 1);
        int useB = (r + c) & 1;
        v = useB ? rf[rel[b] * DIM + idx]
                 : nf[(size_t)sub[b] * DIM + idx];
        g_X[b * NPIX + t] = v;
    }
    __shared__ float ss[512], sq[512];
    ss[t] = v; sq[t] = v * v;
    __syncthreads();
    for (int s = 256; s > 0; s >>= 1) {
        if (t < s) { ss[t] += ss[t + s]; sq[t] += sq[t + s]; }
        __syncthreads();
    }
    if (t == 0) { atomicAdd(&g_sums[0], ss[0]); atomicAdd(&g_sums[1], sq[0]); }
}

// ---------------- per-sample dynamic conv + per-channel stats ----------------
__global__ void k_conv(const float* __restrict__ fw, const int* __restrict__ rel,
                       const float* __restrict__ bn0g, const float* __restrict__ bn0b) {
    int b = blockIdx.x;
    int t = threadIdx.x;   // 256
    __shared__ float xs[22 * 22];
    __shared__ float fs[OCH * 9];

    float invN = 1.0f / (float)(BATCH * NPIX);
    float m0 = g_sums[0] * invN;
    float v0 = g_sums[1] * invN - m0 * m0;
    float sc0 = bn0g[0] * rsqrtf(v0 + EPSF);
    float sh0 = bn0b[0] - sc0 * m0;

    for (int i = t; i < 484; i += 256) {
        int ph = i / 22, pw = i % 22;
        float val = 0.f;
        if (ph >= 1 && ph <= 20 && pw >= 1 && pw <= 20)
            val = sc0 * g_X[b * NPIX + (ph - 1) * 20 + (pw - 1)] + sh0;
        xs[i] = val;
    }
    int rb = rel[b];
    for (int i = t; i < OCH * 9; i += 256) fs[i] = fw[rb * (OCH * 9) + i];
    __syncthreads();

    int oc = t >> 2, l4 = t & 3;
    float f[9];
#pragma unroll
    for (int j = 0; j < 9; j++) f[j] = fs[oc * 9 + j];

    float s1 = 0.f, s2 = 0.f;
    float* ybase = &g_Y[((size_t)b * OCH + oc) * NPIX];
#pragma unroll 4
    for (int s = 0; s < 100; s++) {
        int pix = l4 + 4 * s;
        int h = pix / 20, w = pix % 20;
        const float* xp = &xs[h * 22 + w];
        float acc = xp[0]  * f[0] + xp[1]  * f[1] + xp[2]  * f[2]
                  + xp[22] * f[3] + xp[23] * f[4] + xp[24] * f[5]
                  + xp[44] * f[6] + xp[45] * f[7] + xp[46] * f[8];
        ybase[pix] = acc;
        s1 += acc; s2 += acc * acc;
    }
    s1 += __shfl_down_sync(0xffffffffu, s1, 2, 4);
    s1 += __shfl_down_sync(0xffffffffu, s1, 1, 4);
    s2 += __shfl_down_sync(0xffffffffu, s2, 2, 4);
    s2 += __shfl_down_sync(0xffffffffu, s2, 1, 4);
    if (l4 == 0) { atomicAdd(&g_csum[oc], s1); atomicAdd(&g_csumsq[oc], s2); }
}

// ---------------- compose the two BN2d ----------------
__global__ void k_chan(const float* __restrict__ cg, const float* __restrict__ cb,
                       const float* __restrict__ b1g, const float* __restrict__ b1b) {
    int t = threadIdx.x;
    if (t >= OCH) return;
    float invN = 1.0f / (float)(BATCH * NPIX);
    float m = g_csum[t] * invN;
    float v = g_csumsq[t] * invN - m * m;
    float t1 = rsqrtf(v + EPSF);
    float var1 = cg[t] * cg[t] * v * t1 * t1;
    float t2 = rsqrtf(var1 + EPSF);
    float sc = b1g[t] * cg[t] * t1 * t2;
    g_scale[t] = sc;
    g_shift[t] = b1b[t] - sc * m;
}

// ---------------- build B' = [Bh | Bl | Bh] from n_feats ----------------
__global__ void k_cvt_nf(const float* __restrict__ nf) {
    int n = blockIdx.x;      // 0..NENTP-1
    int k = threadIdx.x;     // 0..255
    float x = 0.f;
    if (n < NENT && k < DIM) x = nf[(size_t)n * DIM + k];
    __nv_bfloat16 hi = __float2bfloat16(x);
    float lo = x - __bfloat162float(hi);
    __nv_bfloat16 lo16 = __float2bfloat16(lo);
    size_t base = (size_t)n * KTOT + k;
    g_bp[base] = hi;
    g_bp[base + KPASS] = lo16;
    g_bp[base + 2 * KPASS] = hi;
}

// ---------------- fc_w -> bf16 hi/lo ----------------
__global__ void k_cvt_fcw(const float* __restrict__ fw) {
    int n = blockIdx.x;      // 0..199
    int t = threadIdx.x;     // 256
#pragma unroll 4
    for (int i = 0; i < 100; i++) {
        size_t idx = (size_t)n * FLATK + t + 256 * i;
        float x = fw[idx];
        __nv_bfloat16 hi = __float2bfloat16(x);
        g_wh[idx] = hi;
        g_wl[idx] = __float2bfloat16(x - __bfloat162float(hi));
    }
}

// ---------------- bn(Y)+relu -> bf16 hi/lo ----------------
__global__ void k_prepA() {
    int m = blockIdx.x;      // 0..2047
    int t = threadIdx.x;     // 256
    __shared__ float sc[OCH], sh[OCH];
    if (t < OCH) { sc[t] = g_scale[t]; sh[t] = g_shift[t]; }
    __syncthreads();
#pragma unroll 4
    for (int i = 0; i < 100; i++) {
        int k = t + 256 * i;
        int oc = k / NPIX;
        size_t idx = (size_t)m * FLATK + k;
        float z = sc[oc] * g_Y[idx] + sh[oc];
        z = z > 0.f ? z : 0.f;
        __nv_bfloat16 hi = __float2bfloat16(z);
        g_yh[idx] = hi;
        g_yl[idx] = __float2bfloat16(z - __bfloat162float(hi));
    }
}

// ---------------- mma.sync helpers ----------------
__device__ __forceinline__ uint32_t cvta_smem(const void* p) {
    uint32_t a;
    asm("{ .reg .u64 t; cvta.to.shared.u64 t, %1; cvt.u32.u64 %0, t; }" : "=r"(a) : "l"(p));
    return a;
}
__device__ __forceinline__ void cp16(uint32_t dst, const void* src, uint32_t sz) {
    asm volatile("cp.async.cg.shared.global [%0], [%1], 16, %2;"
                 :: "r"(dst), "l"(src), "r"(sz));
}
__device__ __forceinline__ void cp_commit() {
    asm volatile("cp.async.commit_group;");
}
template <int N>
__device__ __forceinline__ void cp_wait() {
    asm volatile("cp.async.wait_group %0;" :: "n"(N));
}
__device__ __forceinline__ void ldsm_x4(uint32_t& r0, uint32_t& r1, uint32_t& r2, uint32_t& r3,
                                        uint32_t addr) {
    asm volatile("ldmatrix.sync.aligned.m8n8.x4.shared.b16 {%0,%1,%2,%3}, [%4];"
                 : "=r"(r0), "=r"(r1), "=r"(r2), "=r"(r3) : "r"(addr));
}
__device__ __forceinline__ void mma_bf16(float& d0, float& d1, float& d2, float& d3,
                                         uint32_t a0, uint32_t a1, uint32_t a2, uint32_t a3,
                                         uint32_t b0, uint32_t b1) {
    asm volatile("mma.sync.aligned.m16n8k16.row.col.f32.bf16.bf16.f32 "
                 "{%0,%1,%2,%3}, {%4,%5,%6,%7}, {%8,%9}, {%0,%1,%2,%3};"
                 : "+f"(d0), "+f"(d1), "+f"(d2), "+f"(d3)
                 : "r"(a0), "r"(a1), "r"(a2), "r"(a3), "r"(b0), "r"(b1));
}

#define STAGE_BYTES 32768   // 16KB A + 16KB B per stage

// ---------------- scoring GEMM: mma.sync + cp.async double buffer ----------------
__global__ __launch_bounds__(256, 2) void k_out_mma(const float* __restrict__ eb,
                                                    float* __restrict__ out) {
    extern __shared__ __align__(1024) unsigned char dsm[];
    int t = threadIdx.x;
    int lane = t & 31, wid = t >> 5;
    int wm = (wid >> 2) * 64;
    int wn = (wid & 3) * 32;
    int m0 = blockIdx.x * 128;
    int n0 = blockIdx.y * NTILE;

    uint32_t smemBase = cvta_smem(dsm);

    // per-thread load geometry (4 rows of 16B per array)
    int rowL[4]; uint32_t soL[4];
#pragma unroll
    for (int r = 0; r < 4; r++) {
        int e = t + 256 * r;
        rowL[r] = e >> 3;
        int seg = e & 7;
        soL[r] = (uint32_t)rowL[r] * 128 + (uint32_t)((seg ^ (rowL[r] & 7)) << 4);
    }
    const __nv_bfloat16* pA = g_ap + (size_t)m0 * KTOT;
    const __nv_bfloat16* pB = g_bp + (size_t)n0 * KTOT;

    // ldmatrix lane geometry
    int grp = lane >> 3, li = lane & 7;
    int roffA = ((grp & 1) << 3) + li;
    int cgA = grp >> 1;
    int noffB = ((grp >> 1) << 3) + li;
    int cgB = grp & 1;

    float acc[4][4][4];
#pragma unroll
    for (int a = 0; a < 4; a++)
#pragma unroll
        for (int b = 0; b < 4; b++)
#pragma unroll
            for (int c = 0; c < 4; c++) acc[a][b][c] = 0.f;

    auto issue = [&](int ch) {
        uint32_t base = smemBase + (uint32_t)(ch & 1) * STAGE_BYTES;
#pragma unroll
        for (int r = 0; r < 4; r++) {
            size_t go = (size_t)rowL[r] * KTOT + ch * 64 + ((t + 256 * r) & 7) * 8;
            cp16(base + soL[r], pA + go, 16);
            cp16(base + 16384 + soL[r], pB + go, 16);
        }
        cp_commit();
    };

    issue(0);
    for (int ch = 0; ch < 12; ch++) {
        if (ch < 11) { issue(ch + 1); cp_wait<1>(); }
        else cp_wait<0>();
        __syncthreads();
        uint32_t baseA = smemBase + (uint32_t)(ch & 1) * STAGE_BYTES;
        uint32_t baseB = baseA + 16384;
#pragma unroll
        for (int kf = 0; kf < 4; kf++) {
            uint32_t a[4][4];
#pragma unroll
            for (int mf = 0; mf < 4; mf++) {
                int row = wm + mf * 16 + roffA;
                uint32_t addr = baseA + (uint32_t)row * 128
                              + (uint32_t)(((kf * 2 + cgA) ^ li) << 4);
                ldsm_x4(a[mf][0], a[mf][1], a[mf][2], a[mf][3], addr);
            }
            uint32_t b[4][2];
#pragma unroll
            for (int nf2 = 0; nf2 < 2; nf2++) {
                int row = wn + nf2 * 16 + noffB;
                uint32_t addr = baseB + (uint32_t)row * 128
                              + (uint32_t)(((kf * 2 + cgB) ^ li) << 4);
                ldsm_x4(b[nf2 * 2][0], b[nf2 * 2][1], b[nf2 * 2 + 1][0], b[nf2 * 2 + 1][1], addr);
            }
#pragma unroll
            for (int mf = 0; mf < 4; mf++)
#pragma unroll
                for (int nf = 0; nf < 4; nf++)
                    mma_bf16(acc[mf][nf][0], acc[mf][nf][1], acc[mf][nf][2], acc[mf][nf][3],
                             a[mf][0], a[mf][1], a[mf][2], a[mf][3],
                             b[nf][0], b[nf][1]);
        }
        __syncthreads();
    }

    int g = lane >> 2, c = lane & 3;
#pragma unroll
    for (int mf = 0; mf < 4; mf++) {
#pragma unroll
        for (int nf = 0; nf < 4; nf++) {
            int n = n0 + wn + nf * 8 + c * 2;
            if (n < NENT) {
                float2 bias = *(const float2*)(eb + n);
                int m = m0 + wm + mf * 16 + g;
                float2 v0 = {acc[mf][nf][0] + bias.x, acc[mf][nf][1] + bias.y};
                *(float2*)(out + (size_t)m * NENT + n) = v0;
                float2 v1 = {acc[mf][nf][2] + bias.x, acc[mf][nf][3] + bias.y};
                *(float2*)(out + (size_t)(m + 8) * NENT + n) = v1;
            }
        }
    }
}

// ---------------- FC GEMM: mma.sync, 3 logical passes, K-split ----------------
// grid: (2 N-tiles, 16 M-tiles, KSPLIT), CTA 128x128, chunks of 64 over K.
#define FC_CHUNKS 150   // 3 passes x 50 chunks (KSEG/64)

__global__ __launch_bounds__(256, 2) void k_fc_mma() {
    extern __shared__ __align__(1024) unsigned char dsm[];
    int t = threadIdx.x;
    int lane = t & 31, wid = t >> 5;
    int wm = (wid >> 2) * 64;
    int wn = (wid & 3) * 32;
    int n0 = blockIdx.x * 128;
    int m0 = blockIdx.y * 128;
    int ks = blockIdx.z;
    size_t kbase = (size_t)ks * KSEG;

    uint32_t smemBase = cvta_smem(dsm);

    int rowL[4]; uint32_t soL[4]; int segL[4];
#pragma unroll
    for (int r = 0; r < 4; r++) {
        int e = t + 256 * r;
        rowL[r] = e >> 3;
        segL[r] = e & 7;
        soL[r] = (uint32_t)rowL[r] * 128 + (uint32_t)((segL[r] ^ (rowL[r] & 7)) << 4);
    }

    int grp = lane >> 3, li = lane & 7;
    int roffA = ((grp & 1) << 3) + li;
    int cgA = grp >> 1;
    int noffB = ((grp >> 1) << 3) + li;
    int cgB = grp & 1;

    float acc[4][4][4];
#pragma unroll
    for (int a = 0; a < 4; a++)
#pragma unroll
        for (int b = 0; b < 4; b++)
#pragma unroll
            for (int c = 0; c < 4; c++) acc[a][b][c] = 0.f;

    auto issue = [&](int idx) {
        int p = idx / 50, c = idx - p * 50;
        const __nv_bfloat16* Ab = (p == 2) ? g_yl : g_yh;
        const __nv_bfloat16* Bb = (p == 1) ? g_wl : g_wh;
        size_t koff = kbase + (size_t)c * 64;
        uint32_t base = smemBase + (uint32_t)(idx & 1) * STAGE_BYTES;
#pragma unroll
        for (int r = 0; r < 4; r++) {
            size_t ga = (size_t)(m0 + rowL[r]) * FLATK + koff + segL[r] * 8;
            cp16(base + soL[r], Ab + ga, 16);
            int nrow = n0 + rowL[r];
            int ok = nrow < DIM;
            size_t gb = (size_t)(ok ? nrow : 0) * FLATK + koff + segL[r] * 8;
            cp16(base + 16384 + soL[r], Bb + gb, ok ? 16u : 0u);
        }
        cp_commit();
    };

    issue(0);
    for (int ch = 0; ch < FC_CHUNKS; ch++) {
        if (ch < FC_CHUNKS - 1) { issue(ch + 1); cp_wait<1>(); }
        else cp_wait<0>();
        __syncthreads();
        uint32_t baseA = smemBase + (uint32_t)(ch & 1) * STAGE_BYTES;
        uint32_t baseB = baseA + 16384;
#pragma unroll
        for (int kf = 0; kf < 4; kf++) {
            uint32_t a[4][4];
#pragma unroll
            for (int mf = 0; mf < 4; mf++) {
                int row = wm + mf * 16 + roffA;
                uint32_t addr = baseA + (uint32_t)row * 128
                              + (uint32_t)(((kf * 2 + cgA) ^ li) << 4);
                ldsm_x4(a[mf][0], a[mf][1], a[mf][2], a[mf][3], addr);
            }
            uint32_t b[4][2];
#pragma unroll
            for (int nf2 = 0; nf2 < 2; nf2++) {
                int row = wn + nf2 * 16 + noffB;
                uint32_t addr = baseB + (uint32_t)row * 128
                              + (uint32_t)(((kf * 2 + cgB) ^ li) << 4);
                ldsm_x4(b[nf2 * 2][0], b[nf2 * 2][1], b[nf2 * 2 + 1][0], b[nf2 * 2 + 1][1], addr);
            }
#pragma unroll
            for (int mf = 0; mf < 4; mf++)
#pragma unroll
                for (int nf = 0; nf < 4; nf++)
                    mma_bf16(acc[mf][nf][0], acc[mf][nf][1], acc[mf][nf][2], acc[mf][nf][3],
                             a[mf][0], a[mf][1], a[mf][2], a[mf][3],
                             b[nf][0], b[nf][1]);
        }
        __syncthreads();
    }

    // store partials (fp32), layout [ks][BATCH][NPADFC]
    int g = lane >> 2, c = lane & 3;
    float* hp = g_hp + (size_t)ks * BATCH * NPADFC;
#pragma unroll
    for (int mf = 0; mf < 4; mf++) {
#pragma unroll
        for (int nf = 0; nf < 4; nf++) {
            int n = n0 + wn + nf * 8 + c * 2;
            int m = m0 + wm + mf * 16 + g;
            float2 v0 = {acc[mf][nf][0], acc[mf][nf][1]};
            *(float2*)(hp + (size_t)m * NPADFC + n) = v0;
            float2 v1 = {acc[mf][nf][2], acc[mf][nf][3]};
            *(float2*)(hp + (size_t)(m + 8) * NPADFC + n) = v1;
        }
    }
}

// ---------------- reduce fc partials + bias ----------------
__global__ void k_fcred(const float* __restrict__ fb) {
    int m = blockIdx.x;
    int t = threadIdx.x;
    if (t >= DIM) return;
    float s = fb[t];
#pragma unroll
    for (int z = 0; z < KSPLIT; z++)
        s += g_hp[((size_t)z * BATCH + m) * NPADFC + t];
    g_H[m * DIM + t] = s;
}

// ---------------- bn1d + relu -> A' = [Ah | Ah | Al] ----------------
__global__ void k_bn1d(const float* __restrict__ b2g, const float* __restrict__ b2b) {
    int d = blockIdx.x;     // 0..255
    int t = threadIdx.x;    // 256
    __nv_bfloat16 z16 = __float2bfloat16(0.f);
    if (d >= DIM) {
        for (int i = t; i < BATCH; i += 256) {
            size_t base = (size_t)i * KTOT + d;
            g_ap[base] = z16; g_ap[base + KPASS] = z16; g_ap[base + 2 * KPASS] = z16;
        }
        return;
    }
    float vals[8];
    float s1 = 0.f, s2 = 0.f;
#pragma unroll
    for (int i = 0; i < 8; i++) {
        float h = g_H[(t + 256 * i) * DIM + d];
        vals[i] = h; s1 += h; s2 += h * h;
    }
    __shared__ float ss[256], sq[256];
    ss[t] = s1; sq[t] = s2;
    __syncthreads();
    for (int s = 128; s > 0; s >>= 1) {
        if (t < s) { ss[t] += ss[t + s]; sq[t] += sq[t + s]; }
        __syncthreads();
    }
    __shared__ float ssc, ssh;
    if (t == 0) {
        float m = ss[0] / (float)BATCH;
        float v = sq[0] / (float)BATCH - m * m;
        float sc = b2g[d] * rsqrtf(v + EPSF);
        ssc = sc; ssh = b2b[d] - sc * m;
    }
    __syncthreads();
    float sc = ssc, sh = ssh;
#pragma unroll
    for (int i = 0; i < 8; i++) {
        float z = sc * vals[i] + sh;
        z = z > 0.f ? z : 0.f;
        __nv_bfloat16 hi = __float2bfloat16(z);
        float lo = z - __bfloat162float(hi);
        size_t base = (size_t)(t + 256 * i) * KTOT + d;
        g_ap[base] = hi;
        g_ap[base + KPASS] = hi;
        g_ap[base + 2 * KPASS] = __float2bfloat16(lo);
    }
}

// ---------------- launch ----------------
extern "C" void kernel_launch(void* const* d_in, const int* in_sizes, int n_in,
                              void* d_out, int out_size) {
    const float* nf   = (const float*)d_in[0];
    const float* rf   = (const float*)d_in[1];
    const float* fw   = (const float*)d_in[2];
    const float* bn0g = (const float*)d_in[3];
    const float* bn0b = (const float*)d_in[4];
    const float* cbng = (const float*)d_in[5];
    const float* cbnb = (const float*)d_in[6];
    const float* bn1g = (const float*)d_in[7];
    const float* bn1b = (const float*)d_in[8];
    const float* fcw  = (const float*)d_in[9];
    const float* fcb  = (const float*)d_in[10];
    const float* bn2g = (const float*)d_in[11];
    const float* bn2b = (const float*)d_in[12];
    const float* eb   = (const float*)d_in[13];
    const int*   sub  = (const int*)d_in[14];
    const int*   rel  = (const int*)d_in[15];
    float* out = (float*)d_out;

    cudaFuncSetAttribute(k_out_mma, cudaFuncAttributeMaxDynamicSharedMemorySize, 2 * STAGE_BYTES);
    cudaFuncSetAttribute(k_fc_mma, cudaFuncAttributeMaxDynamicSharedMemorySize, 2 * STAGE_BYTES);

    k_init<<<1, 256>>>();
    k_gather<<<BATCH, 512>>>(nf, rf, sub, rel);
    k_conv<<<BATCH, 256>>>(fw, rel, bn0g, bn0b);
    k_chan<<<1, 64>>>(cbng, cbnb, bn1g, bn1b);
    k_cvt_nf<<<NENTP, 256>>>(nf);
    k_cvt_fcw<<<DIM, 256>>>(fcw);
    k_prepA<<<BATCH, 256>>>();
    k_fc_mma<<<dim3(2, 16, KSPLIT), 256, 2 * STAGE_BYTES>>>();
    k_fcred<<<BATCH, 256>>>(fcb);
    k_bn1d<<<KPASS, 256>>>(bn2g, bn2b);
    k_out_mma<<<dim3(16, NTILES), 256, 2 * STAGE_BYTES>>>(eb, out);
}

// round 8
// speedup vs baseline: 6.7760x; 1.1573x over previous
#include <cuda_runtime.h>
#include <cuda_fp16.h>
#include <math.h>
#include <stdint.h>

#define BATCH   2048
#define DIM     200
#define OCH     64
#define NPIX    400          // 20x20
#define FLATK   25600        // 64*400
#define NENT    50000
#define EPSF    1e-5f

#define KPASS   256          // padded K per pass (200 -> 256)
#define KTOT2   512          // scoring A': [Ah | Al]
#define NTILE   128
#define NTILES  391
#define NENTP   (NTILES*NTILE)   // 50048
#define KSPLIT  8
#define KSEG    (FLATK/KSPLIT)   // 3200
#define NPADFC  256
#define FC_CHUNKS 100        // 2 passes x 50 chunks

// ---------------- scratch ----------------
__device__ float g_X[BATCH * NPIX];
__device__ float g_H[BATCH * DIM];
__device__ float g_sums[2];
__device__ float g_csum[OCH];
__device__ float g_csumsq[OCH];
__device__ float g_scale[OCH];
__device__ float g_shift[OCH];
__device__ __half g_ap[(size_t)BATCH * KTOT2];      // scoring A' [Ah|Al] 2MB
__device__ __half g_bp[(size_t)NENTP * KPASS];      // scoring B (hi only) 25.6MB
__device__ __half g_yh[(size_t)BATCH * FLATK];      // fc A hi 105MB
__device__ __half g_yl[(size_t)BATCH * FLATK];      // fc A lo 105MB
__device__ __half g_wh[(size_t)DIM * FLATK];        // fc W hi 10.3MB
__device__ float g_hp[(size_t)KSPLIT * BATCH * NPADFC];

// ---------------- init ----------------
__global__ void k_init() {
    int t = threadIdx.x;
    if (t < 2) g_sums[t] = 0.f;
    if (t < OCH) { g_csum[t] = 0.f; g_csumsq[t] = 0.f; }
}

// ---------------- gather + chequer perm + bn0 stats ----------------
__global__ void k_gather(const float* __restrict__ nf, const float* __restrict__ rf,
                         const int* __restrict__ sub, const int* __restrict__ rel) {
    int b = blockIdx.x;
    int t = threadIdx.x;   // 512
    float v = 0.f;
    if (t < NPIX) {
        int r = t / 20, c = t % 20;
        int idx = r * 10 + (c >> 1);
        int useB = (r + c) & 1;
        v = useB ? rf[rel[b] * DIM + idx]
                 : nf[(size_t)sub[b] * DIM + idx];
        g_X[b * NPIX + t] = v;
    }
    __shared__ float ss[512], sq[512];
    ss[t] = v; sq[t] = v * v;
    __syncthreads();
    for (int s = 256; s > 0; s >>= 1) {
        if (t < s) { ss[t] += ss[t + s]; sq[t] += sq[t + s]; }
        __syncthreads();
    }
    if (t == 0) { atomicAdd(&g_sums[0], ss[0]); atomicAdd(&g_sums[1], sq[0]); }
}

// ---------------- conv body (shared by stats and fused passes) ----------------
__device__ __forceinline__ void conv_prologue(int b, int t, float* xs, float* fs,
                                              const float* __restrict__ fw,
                                              const int* __restrict__ rel,
                                              const float* __restrict__ bn0g,
                                              const float* __restrict__ bn0b) {
    float invN = 1.0f / (float)(BATCH * NPIX);
    float m0 = g_sums[0] * invN;
    float v0 = g_sums[1] * invN - m0 * m0;
    float sc0 = bn0g[0] * rsqrtf(v0 + EPSF);
    float sh0 = bn0b[0] - sc0 * m0;
    for (int i = t; i < 484; i += 256) {
        int ph = i / 22, pw = i % 22;
        float val = 0.f;
        if (ph >= 1 && ph <= 20 && pw >= 1 && pw <= 20)
            val = sc0 * g_X[b * NPIX + (ph - 1) * 20 + (pw - 1)] + sh0;
        xs[i] = val;
    }
    int rb = rel[b];
    for (int i = t; i < OCH * 9; i += 256) fs[i] = fw[rb * (OCH * 9) + i];
}

// ---------------- conv pass 1: channel stats only ----------------
__global__ void k_conv_stats(const float* __restrict__ fw, const int* __restrict__ rel,
                             const float* __restrict__ bn0g, const float* __restrict__ bn0b) {
    int b = blockIdx.x;
    int t = threadIdx.x;   // 256
    __shared__ float xs[22 * 22];
    __shared__ float fs[OCH * 9];
    conv_prologue(b, t, xs, fs, fw, rel, bn0g, bn0b);
    __syncthreads();

    int oc = t >> 2, l4 = t & 3;
    float f[9];
#pragma unroll
    for (int j = 0; j < 9; j++) f[j] = fs[oc * 9 + j];

    float s1 = 0.f, s2 = 0.f;
#pragma unroll 4
    for (int s = 0; s < 100; s++) {
        int pix = l4 + 4 * s;
        int h = pix / 20, w = pix % 20;
        const float* xp = &xs[h * 22 + w];
        float acc = xp[0]  * f[0] + xp[1]  * f[1] + xp[2]  * f[2]
                  + xp[22] * f[3] + xp[23] * f[4] + xp[24] * f[5]
                  + xp[44] * f[6] + xp[45] * f[7] + xp[46] * f[8];
        s1 += acc; s2 += acc * acc;
    }
    s1 += __shfl_down_sync(0xffffffffu, s1, 2, 4);
    s1 += __shfl_down_sync(0xffffffffu, s1, 1, 4);
    s2 += __shfl_down_sync(0xffffffffu, s2, 2, 4);
    s2 += __shfl_down_sync(0xffffffffu, s2, 1, 4);
    if (l4 == 0) { atomicAdd(&g_csum[oc], s1); atomicAdd(&g_csumsq[oc], s2); }
}

// ---------------- compose the two BN2d ----------------
__global__ void k_chan(const float* __restrict__ cg, const float* __restrict__ cb,
                       const float* __restrict__ b1g, const float* __restrict__ b1b) {
    int t = threadIdx.x;
    if (t >= OCH) return;
    float invN = 1.0f / (float)(BATCH * NPIX);
    float m = g_csum[t] * invN;
    float v = g_csumsq[t] * invN - m * m;
    float t1 = rsqrtf(v + EPSF);
    float var1 = cg[t] * cg[t] * v * t1 * t1;
    float t2 = rsqrtf(var1 + EPSF);
    float sc = b1g[t] * cg[t] * t1 * t2;
    g_scale[t] = sc;
    g_shift[t] = b1b[t] - sc * m;
}

// ---------------- fc_w -> fp16 hi ----------------
__global__ void k_cvt_fcw(const float* __restrict__ fw) {
    int n = blockIdx.x;      // 0..199
    int t = threadIdx.x;     // 256
#pragma unroll 4
    for (int i = 0; i < 100; i++) {
        size_t idx = (size_t)n * FLATK + t + 256 * i;
        g_wh[idx] = __float2half_rn(fw[idx]);
    }
}

// ---------------- conv pass 2: fused BN+relu -> fp16 hi/lo ----------------
__global__ void k_conv_fused(const float* __restrict__ fw, const int* __restrict__ rel,
                             const float* __restrict__ bn0g, const float* __restrict__ bn0b) {
    int b = blockIdx.x;
    int t = threadIdx.x;   // 256
    __shared__ float xs[22 * 22];
    __shared__ float fs[OCH * 9];
    conv_prologue(b, t, xs, fs, fw, rel, bn0g, bn0b);
    __syncthreads();

    int oc = t >> 2, l4 = t & 3;
    float f[9];
#pragma unroll
    for (int j = 0; j < 9; j++) f[j] = fs[oc * 9 + j];
    float sc = g_scale[oc], sh = g_shift[oc];

    size_t base = ((size_t)b * OCH + oc) * NPIX;
#pragma unroll 4
    for (int s = 0; s < 100; s++) {
        int pix = l4 + 4 * s;
        int h = pix / 20, w = pix % 20;
        const float* xp = &xs[h * 22 + w];
        float acc = xp[0]  * f[0] + xp[1]  * f[1] + xp[2]  * f[2]
                  + xp[22] * f[3] + xp[23] * f[4] + xp[24] * f[5]
                  + xp[44] * f[6] + xp[45] * f[7] + xp[46] * f[8];
        float z = sc * acc + sh;
        z = z > 0.f ? z : 0.f;
        __half hi = __float2half_rn(z);
        g_yh[base + pix] = hi;
        g_yl[base + pix] = __float2half_rn(z - __half2float(hi));
    }
}

// ---------------- n_feats -> fp16 hi (padded) ----------------
__global__ void k_cvt_nf(const float* __restrict__ nf) {
    int n = blockIdx.x;      // 0..NENTP-1
    int k = threadIdx.x;     // 0..255
    float x = 0.f;
    if (n < NENT && k < DIM) x = nf[(size_t)n * DIM + k];
    g_bp[(size_t)n * KPASS + k] = __float2half_rn(x);
}

// ---------------- mma helpers ----------------
__device__ __forceinline__ uint32_t cvta_smem(const void* p) {
    uint32_t a;
    asm("{ .reg .u64 t; cvta.to.shared.u64 t, %1; cvt.u32.u64 %0, t; }" : "=r"(a) : "l"(p));
    return a;
}
__device__ __forceinline__ void cp16(uint32_t dst, const void* src, uint32_t sz) {
    asm volatile("cp.async.cg.shared.global [%0], [%1], 16, %2;"
                 :: "r"(dst), "l"(src), "r"(sz));
}
__device__ __forceinline__ void cp_commit() {
    asm volatile("cp.async.commit_group;");
}
template <int N>
__device__ __forceinline__ void cp_wait() {
    asm volatile("cp.async.wait_group %0;" :: "n"(N));
}
__device__ __forceinline__ void ldsm_x4(uint32_t& r0, uint32_t& r1, uint32_t& r2, uint32_t& r3,
                                        uint32_t addr) {
    asm volatile("ldmatrix.sync.aligned.m8n8.x4.shared.b16 {%0,%1,%2,%3}, [%4];"
                 : "=r"(r0), "=r"(r1), "=r"(r2), "=r"(r3) : "r"(addr));
}
__device__ __forceinline__ void mma_f16(float& d0, float& d1, float& d2, float& d3,
                                        uint32_t a0, uint32_t a1, uint32_t a2, uint32_t a3,
                                        uint32_t b0, uint32_t b1) {
    asm volatile("mma.sync.aligned.m16n8k16.row.col.f32.f16.f16.f32 "
                 "{%0,%1,%2,%3}, {%4,%5,%6,%7}, {%8,%9}, {%0,%1,%2,%3};"
                 : "+f"(d0), "+f"(d1), "+f"(d2), "+f"(d3)
                 : "r"(a0), "r"(a1), "r"(a2), "r"(a3), "r"(b0), "r"(b1));
}

#define STAGE_BYTES 32768

// ---------------- FC GEMM: fp16 2-pass, K-split ----------------
__global__ __launch_bounds__(256, 2) void k_fc_mma() {
    extern __shared__ __align__(1024) unsigned char dsm[];
    int t = threadIdx.x;
    int lane = t & 31, wid = t >> 5;
    int wm = (wid >> 2) * 64;
    int wn = (wid & 3) * 32;
    int n0 = blockIdx.x * 128;
    int m0 = blockIdx.y * 128;
    int ks = blockIdx.z;
    size_t kbase = (size_t)ks * KSEG;

    uint32_t smemBase = cvta_smem(dsm);

    int rowL[4]; uint32_t soL[4]; int segL[4];
#pragma unroll
    for (int r = 0; r < 4; r++) {
        int e = t + 256 * r;
        rowL[r] = e >> 3;
        segL[r] = e & 7;
        soL[r] = (uint32_t)rowL[r] * 128 + (uint32_t)((segL[r] ^ (rowL[r] & 7)) << 4);
    }

    int grp = lane >> 3, li = lane & 7;
    int roffA = ((grp & 1) << 3) + li;
    int cgA = grp >> 1;
    int noffB = ((grp >> 1) << 3) + li;
    int cgB = grp & 1;

    float acc[4][4][4];
#pragma unroll
    for (int a = 0; a < 4; a++)
#pragma unroll
        for (int b = 0; b < 4; b++)
#pragma unroll
            for (int c = 0; c < 4; c++) acc[a][b][c] = 0.f;

    auto issue = [&](int idx) {
        int p = idx / 50, c = idx - p * 50;
        const __half* Ab = p ? g_yl : g_yh;
        size_t koff = kbase + (size_t)c * 64;
        uint32_t base = smemBase + (uint32_t)(idx & 1) * STAGE_BYTES;
#pragma unroll
        for (int r = 0; r < 4; r++) {
            size_t ga = (size_t)(m0 + rowL[r]) * FLATK + koff + segL[r] * 8;
            cp16(base + soL[r], Ab + ga, 16);
            int nrow = n0 + rowL[r];
            int ok = nrow < DIM;
            size_t gb = (size_t)(ok ? nrow : 0) * FLATK + koff + segL[r] * 8;
            cp16(base + 16384 + soL[r], g_wh + gb, ok ? 16u : 0u);
        }
        cp_commit();
    };

    issue(0);
    for (int ch = 0; ch < FC_CHUNKS; ch++) {
        if (ch < FC_CHUNKS - 1) { issue(ch + 1); cp_wait<1>(); }
        else cp_wait<0>();
        __syncthreads();
        uint32_t baseA = smemBase + (uint32_t)(ch & 1) * STAGE_BYTES;
        uint32_t baseB = baseA + 16384;
#pragma unroll
        for (int kf = 0; kf < 4; kf++) {
            uint32_t a[4][4];
#pragma unroll
            for (int mf = 0; mf < 4; mf++) {
                int row = wm + mf * 16 + roffA;
                uint32_t addr = baseA + (uint32_t)row * 128
                              + (uint32_t)(((kf * 2 + cgA) ^ li) << 4);
                ldsm_x4(a[mf][0], a[mf][1], a[mf][2], a[mf][3], addr);
            }
            uint32_t b[4][2];
#pragma unroll
            for (int nf2 = 0; nf2 < 2; nf2++) {
                int row = wn + nf2 * 16 + noffB;
                uint32_t addr = baseB + (uint32_t)row * 128
                              + (uint32_t)(((kf * 2 + cgB) ^ li) << 4);
                ldsm_x4(b[nf2 * 2][0], b[nf2 * 2][1], b[nf2 * 2 + 1][0], b[nf2 * 2 + 1][1], addr);
            }
#pragma unroll
            for (int mf = 0; mf < 4; mf++)
#pragma unroll
                for (int nf = 0; nf < 4; nf++)
                    mma_f16(acc[mf][nf][0], acc[mf][nf][1], acc[mf][nf][2], acc[mf][nf][3],
                            a[mf][0], a[mf][1], a[mf][2], a[mf][3],
                            b[nf][0], b[nf][1]);
        }
        __syncthreads();
    }

    int g = lane >> 2, c = lane & 3;
    float* hp = g_hp + (size_t)ks * BATCH * NPADFC;
#pragma unroll
    for (int mf = 0; mf < 4; mf++) {
#pragma unroll
        for (int nf = 0; nf < 4; nf++) {
            int n = n0 + wn + nf * 8 + c * 2;
            int m = m0 + wm + mf * 16 + g;
            float2 v0 = {acc[mf][nf][0], acc[mf][nf][1]};
            *(float2*)(hp + (size_t)m * NPADFC + n) = v0;
            float2 v1 = {acc[mf][nf][2], acc[mf][nf][3]};
            *(float2*)(hp + (size_t)(m + 8) * NPADFC + n) = v1;
        }
    }
}

// ---------------- reduce fc partials + bias ----------------
__global__ void k_fcred(const float* __restrict__ fb) {
    int m = blockIdx.x;
    int t = threadIdx.x;
    if (t >= DIM) return;
    float s = fb[t];
#pragma unroll
    for (int z = 0; z < KSPLIT; z++)
        s += g_hp[((size_t)z * BATCH + m) * NPADFC + t];
    g_H[m * DIM + t] = s;
}

// ---------------- bn1d + relu -> A' = [Ah | Al] fp16 ----------------
__global__ void k_bn1d(const float* __restrict__ b2g, const float* __restrict__ b2b) {
    int d = blockIdx.x;     // 0..255
    int t = threadIdx.x;    // 256
    __half z16 = __float2half_rn(0.f);
    if (d >= DIM) {
        for (int i = t; i < BATCH; i += 256) {
            size_t base = (size_t)i * KTOT2 + d;
            g_ap[base] = z16; g_ap[base + KPASS] = z16;
        }
        return;
    }
    float vals[8];
    float s1 = 0.f, s2 = 0.f;
#pragma unroll
    for (int i = 0; i < 8; i++) {
        float h = g_H[(t + 256 * i) * DIM + d];
        vals[i] = h; s1 += h; s2 += h * h;
    }
    __shared__ float ss[256], sq[256];
    ss[t] = s1; sq[t] = s2;
    __syncthreads();
    for (int s = 128; s > 0; s >>= 1) {
        if (t < s) { ss[t] += ss[t + s]; sq[t] += sq[t + s]; }
        __syncthreads();
    }
    __shared__ float ssc, ssh;
    if (t == 0) {
        float m = ss[0] / (float)BATCH;
        float v = sq[0] / (float)BATCH - m * m;
        float sc = b2g[d] * rsqrtf(v + EPSF);
        ssc = sc; ssh = b2b[d] - sc * m;
    }
    __syncthreads();
    float sc = ssc, sh = ssh;
#pragma unroll
    for (int i = 0; i < 8; i++) {
        float z = sc * vals[i] + sh;
        z = z > 0.f ? z : 0.f;
        __half hi = __float2half_rn(z);
        size_t base = (size_t)(t + 256 * i) * KTOT2 + d;
        g_ap[base] = hi;
        g_ap[base + KPASS] = __float2half_rn(z - __half2float(hi));
    }
}

// ---------------- scoring GEMM: fp16 2-pass, K'=512 ----------------
__global__ __launch_bounds__(256, 2) void k_out_mma(const float* __restrict__ eb,
                                                    float* __restrict__ out) {
    extern __shared__ __align__(1024) unsigned char dsm[];
    int t = threadIdx.x;
    int lane = t & 31, wid = t >> 5;
    int wm = (wid >> 2) * 64;
    int wn = (wid & 3) * 32;
    int m0 = blockIdx.x * 128;
    int n0 = blockIdx.y * NTILE;

    uint32_t smemBase = cvta_smem(dsm);

    int rowL[4]; uint32_t soL[4]; int segL[4];
#pragma unroll
    for (int r = 0; r < 4; r++) {
        int e = t + 256 * r;
        rowL[r] = e >> 3;
        segL[r] = e & 7;
        soL[r] = (uint32_t)rowL[r] * 128 + (uint32_t)((segL[r] ^ (rowL[r] & 7)) << 4);
    }
    const __half* pA = g_ap + (size_t)m0 * KTOT2;
    const __half* pB = g_bp + (size_t)n0 * KPASS;

    int grp = lane >> 3, li = lane & 7;
    int roffA = ((grp & 1) << 3) + li;
    int cgA = grp >> 1;
    int noffB = ((grp >> 1) << 3) + li;
    int cgB = grp & 1;

    float acc[4][4][4];
#pragma unroll
    for (int a = 0; a < 4; a++)
#pragma unroll
        for (int b = 0; b < 4; b++)
#pragma unroll
            for (int c = 0; c < 4; c++) acc[a][b][c] = 0.f;

    auto issue = [&](int ch) {
        uint32_t base = smemBase + (uint32_t)(ch & 1) * STAGE_BYTES;
        int cb = ch & 3;   // B repeats over the two passes
#pragma unroll
        for (int r = 0; r < 4; r++) {
            size_t ga = (size_t)rowL[r] * KTOT2 + ch * 64 + segL[r] * 8;
            cp16(base + soL[r], pA + ga, 16);
            size_t gb = (size_t)rowL[r] * KPASS + cb * 64 + segL[r] * 8;
            cp16(base + 16384 + soL[r], pB + gb, 16);
        }
        cp_commit();
    };

    issue(0);
    for (int ch = 0; ch < 8; ch++) {
        if (ch < 7) { issue(ch + 1); cp_wait<1>(); }
        else cp_wait<0>();
        __syncthreads();
        uint32_t baseA = smemBase + (uint32_t)(ch & 1) * STAGE_BYTES;
        uint32_t baseB = baseA + 16384;
#pragma unroll
        for (int kf = 0; kf < 4; kf++) {
            uint32_t a[4][4];
#pragma unroll
            for (int mf = 0; mf < 4; mf++) {
                int row = wm + mf * 16 + roffA;
                uint32_t addr = baseA + (uint32_t)row * 128
                              + (uint32_t)(((kf * 2 + cgA) ^ li) << 4);
                ldsm_x4(a[mf][0], a[mf][1], a[mf][2], a[mf][3], addr);
            }
            uint32_t b[4][2];
#pragma unroll
            for (int nf2 = 0; nf2 < 2; nf2++) {
                int row = wn + nf2 * 16 + noffB;
                uint32_t addr = baseB + (uint32_t)row * 128
                              + (uint32_t)(((kf * 2 + cgB) ^ li) << 4);
                ldsm_x4(b[nf2 * 2][0], b[nf2 * 2][1], b[nf2 * 2 + 1][0], b[nf2 * 2 + 1][1], addr);
            }
#pragma unroll
            for (int mf = 0; mf < 4; mf++)
#pragma unroll
                for (int nf = 0; nf < 4; nf++)
                    mma_f16(acc[mf][nf][0], acc[mf][nf][1], acc[mf][nf][2], acc[mf][nf][3],
                            a[mf][0], a[mf][1], a[mf][2], a[mf][3],
                            b[nf][0], b[nf][1]);
        }
        __syncthreads();
    }

    int g = lane >> 2, c = lane & 3;
#pragma unroll
    for (int mf = 0; mf < 4; mf++) {
#pragma unroll
        for (int nf = 0; nf < 4; nf++) {
            int n = n0 + wn + nf * 8 + c * 2;
            if (n < NENT) {
                float2 bias = *(const float2*)(eb + n);
                int m = m0 + wm + mf * 16 + g;
                float2 v0 = {acc[mf][nf][0] + bias.x, acc[mf][nf][1] + bias.y};
                *(float2*)(out + (size_t)m * NENT + n) = v0;
                float2 v1 = {acc[mf][nf][2] + bias.x, acc[mf][nf][3] + bias.y};
                *(float2*)(out + (size_t)(m + 8) * NENT + n) = v1;
            }
        }
    }
}

// ---------------- launch ----------------
extern "C" void kernel_launch(void* const* d_in, const int* in_sizes, int n_in,
                              void* d_out, int out_size) {
    const float* nf   = (const float*)d_in[0];
    const float* rf   = (const float*)d_in[1];
    const float* fw   = (const float*)d_in[2];
    const float* bn0g = (const float*)d_in[3];
    const float* bn0b = (const float*)d_in[4];
    const float* cbng = (const float*)d_in[5];
    const float* cbnb = (const float*)d_in[6];
    const float* bn1g = (const float*)d_in[7];
    const float* bn1b = (const float*)d_in[8];
    const float* fcw  = (const float*)d_in[9];
    const float* fcb  = (const float*)d_in[10];
    const float* bn2g = (const float*)d_in[11];
    const float* bn2b = (const float*)d_in[12];
    const float* eb   = (const float*)d_in[13];
    const int*   sub  = (const int*)d_in[14];
    const int*   rel  = (const int*)d_in[15];
    float* out = (float*)d_out;

    cudaFuncSetAttribute(k_out_mma, cudaFuncAttributeMaxDynamicSharedMemorySize, 2 * STAGE_BYTES);
    cudaFuncSetAttribute(k_fc_mma, cudaFuncAttributeMaxDynamicSharedMemorySize, 2 * STAGE_BYTES);

    k_init<<<1, 256>>>();
    k_gather<<<BATCH, 512>>>(nf, rf, sub, rel);
    k_conv_stats<<<BATCH, 256>>>(fw, rel, bn0g, bn0b);
    k_chan<<<1, 64>>>(cbng, cbnb, bn1g, bn1b);
    k_cvt_fcw<<<DIM, 256>>>(fcw);
    k_conv_fused<<<BATCH, 256>>>(fw, rel, bn0g, bn0b);
    k_cvt_nf<<<NENTP, 256>>>(nf);
    k_fc_mma<<<dim3(2, 16, KSPLIT), 256, 2 * STAGE_BYTES>>>();
    k_fcred<<<BATCH, 256>>>(fcb);
    k_bn1d<<<KPASS, 256>>>(bn2g, bn2b);
    k_out_mma<<<dim3(16, NTILES), 256, 2 * STAGE_BYTES>>>(eb, out);
}